// round 4
// baseline (speedup 1.0000x reference)
#include <cuda_runtime.h>
#include <math.h>

#define L_LAYERS 16
#define T_LEN 65536
#define B_SZ 8
#define TT 512
#define HALO 1024
#define NT (TT + HALO)
#define NTHREADS 256

// ---------------- device scratch (precomputed folded weights) ----------------
__device__ float g_wfg[L_LAYERS][32][8];   // per channel: wf0,wf1,wf2,bf_eff, wg0,wg1,wg2,bg_eff
__device__ float g_Mt[L_LAYERS][32][64];   // M[i] = W_sk1 @ W_s[i], stored transposed [c][sc]
__device__ float g_wo[L_LAYERS][32];
__device__ float g_bo[L_LAYERS];
__device__ float g_head[200];              // [0:64) b1_eff, [64:128) Wsk2 row0, [128:192) Wsk2 row1, [192] b_sk2[0], [193] b_sk2[1]

// ---------------- weight folding kernel ----------------
__global__ void wn_precompute(
    const float* __restrict__ W_in, const float* __restrict__ b_in,
    const float* __restrict__ W_f,  const float* __restrict__ b_f,
    const float* __restrict__ W_g,  const float* __restrict__ b_g,
    const float* __restrict__ W_s,  const float* __restrict__ b_s,
    const float* __restrict__ W_o,  const float* __restrict__ b_o,
    const float* __restrict__ W_sk1,const float* __restrict__ b_sk1,
    const float* __restrict__ W_sk2,const float* __restrict__ b_sk2)
{
    int i = blockIdx.x;       // layer
    int tid = threadIdx.x;

    // wf_eff[c][k] = sum_c' W_f[i,c,c',k] * W_in[i,c']   (same for g)
    for (int idx = tid; idx < 32 * 3; idx += NTHREADS) {
        int c = idx / 3, k = idx % 3;
        float sf = 0.f, sg = 0.f;
        for (int cp = 0; cp < 32; ++cp) {
            float win = W_in[i * 32 + cp];
            sf += W_f[((i * 32 + c) * 32 + cp) * 3 + k] * win;
            sg += W_g[((i * 32 + c) * 32 + cp) * 3 + k] * win;
        }
        g_wfg[i][c][k]     = sf;
        g_wfg[i][c][4 + k] = sg;
    }
    // bias fold: bf_eff[c] = b_f + sum_k sum_c' W_f[i,c,c',k] * b_in[i,c']
    if (tid < 32) {
        int c = tid;
        float bf = b_f[i * 32 + c], bg = b_g[i * 32 + c];
        for (int k = 0; k < 3; ++k)
            for (int cp = 0; cp < 32; ++cp) {
                float bi = b_in[i * 32 + cp];
                bf += W_f[((i * 32 + c) * 32 + cp) * 3 + k] * bi;
                bg += W_g[((i * 32 + c) * 32 + cp) * 3 + k] * bi;
            }
        g_wfg[i][c][3] = bf;
        g_wfg[i][c][7] = bg;
        g_wo[i][c] = W_o[i * 32 + c];
    }
    if (tid == 0) g_bo[i] = b_o[i];

    // M_t[i][c][sc] = sum_sc' W_sk1[sc,sc'] * W_s[i,sc',c]
    for (int idx = tid; idx < 2048; idx += NTHREADS) {
        int c = idx >> 6, sc = idx & 63;
        float s = 0.f;
        for (int scp = 0; scp < 64; ++scp)
            s += W_sk1[sc * 64 + scp] * W_s[(i * 64 + scp) * 32 + c];
        g_Mt[i][c][sc] = s;
    }

    // head constants (block 0 only)
    if (i == 0) {
        if (tid < 64) {
            int sc = tid;
            float s = b_sk1[sc];
            for (int scp = 0; scp < 64; ++scp) {
                float bsum = 0.f;
                for (int l = 0; l < L_LAYERS; ++l) bsum += b_s[l * 64 + scp];
                s += W_sk1[sc * 64 + scp] * bsum;
            }
            g_head[sc]        = s;
            g_head[64 + sc]   = W_sk2[sc];       // out row 0 (means)
            g_head[128 + sc]  = W_sk2[64 + sc];  // out row 1 (log-var)
        }
        if (tid == 0) { g_head[192] = b_sk2[0]; g_head[193] = b_sk2[1]; }
    }
}

// tanh(uf) * sigmoid(ug) with a single reciprocal:
//   tanh(uf) = (e^{2uf}-1)/(e^{2uf}+1),  sigmoid(ug) = 1/(1+e^{-ug})
__device__ __forceinline__ float gatedfn(float uf, float ug) {
    float ef = __expf(2.0f * uf);
    float eg = __expf(-ug);
    float num = ef - 1.0f;
    float den = (ef + 1.0f) * (1.0f + eg);
    return __fdividef(num, den);
}

// ---------------- main kernel ----------------
__global__ __launch_bounds__(NTHREADS) void wn_main(
    const float* __restrict__ x, float* __restrict__ out)
{
    __shared__ __align__(16) float sbuf[2][NT];
    __shared__ __align__(16) float s_wfg[32][8];
    __shared__ __align__(16) float s_Mt[32][64];
    __shared__ float s_wo[32];
    __shared__ float s_head[200];
    __shared__ float s_bo;

    const int b   = blockIdx.y;
    const int t0  = blockIdx.x * TT;
    const int tid = threadIdx.x;

    // load 1-channel input stream (zero-pad for global t < 0)
    const float* xb = x + (size_t)b * T_LEN;
    for (int p = tid; p < NT; p += NTHREADS) {
        int g = t0 - HALO + p;
        sbuf[0][p] = (g >= 0) ? xb[g] : 0.0f;
    }
    for (int idx = tid; idx < 200; idx += NTHREADS) s_head[idx] = g_head[idx];

    // register-resident skip accumulators: 2 timesteps per thread
    float skipA[64], skipB[64];
    #pragma unroll
    for (int sc = 0; sc < 64; ++sc) { skipA[sc] = 0.f; skipB[sc] = 0.f; }

    int cur = 0;
    int off = 0;                       // buffer valid from this index
    const int p0 = HALO + tid;
    const int p1 = HALO + tid + NTHREADS;

    for (int layer = 0; layer < L_LAYERS; ++layer) {
        const int d = 1 << (layer & 7);

        __syncthreads();               // prior layer done reading weights + buffers
        // stage this layer's weights into smem
        ((float*)s_wfg)[tid] = (&g_wfg[layer][0][0])[tid];   // 256 floats
        for (int idx = tid; idx < 2048; idx += NTHREADS)
            ((float*)s_Mt)[idx] = (&g_Mt[layer][0][0])[idx];
        if (tid < 32) s_wo[tid] = g_wo[layer][tid];
        if (tid == 0) s_bo = g_bo[layer];
        __syncthreads();

        const float* cb = sbuf[cur];
        float* nb = sbuf[cur ^ 1];

        // ---- output positions: gated + skip + residual update ----
        float a0 = cb[p0], e0 = cb[p0 - d], f0 = cb[p0 - 2 * d];
        float a1 = cb[p1], e1 = cb[p1 - d], f1 = cb[p1 - 2 * d];
        float dot0 = 0.f, dot1 = 0.f;
        #pragma unroll 2
        for (int c = 0; c < 32; ++c) {
            float4 wf = *(const float4*)&s_wfg[c][0];
            float4 wg = *(const float4*)&s_wfg[c][4];
            float uf0 = fmaf(wf.x, f0, fmaf(wf.y, e0, fmaf(wf.z, a0, wf.w)));
            float ug0 = fmaf(wg.x, f0, fmaf(wg.y, e0, fmaf(wg.z, a0, wg.w)));
            float uf1 = fmaf(wf.x, f1, fmaf(wf.y, e1, fmaf(wf.z, a1, wf.w)));
            float ug1 = fmaf(wg.x, f1, fmaf(wg.y, e1, fmaf(wg.z, a1, wg.w)));
            float gc0 = gatedfn(uf0, ug0);
            float gc1 = gatedfn(uf1, ug1);
            float wo = s_wo[c];
            dot0 = fmaf(wo, gc0, dot0);
            dot1 = fmaf(wo, gc1, dot1);
            const float4* Mrow = (const float4*)&s_Mt[c][0];
            #pragma unroll
            for (int q = 0; q < 16; ++q) {
                float4 m = Mrow[q];
                skipA[4*q+0] = fmaf(m.x, gc0, skipA[4*q+0]);
                skipA[4*q+1] = fmaf(m.y, gc0, skipA[4*q+1]);
                skipA[4*q+2] = fmaf(m.z, gc0, skipA[4*q+2]);
                skipA[4*q+3] = fmaf(m.w, gc0, skipA[4*q+3]);
                skipB[4*q+0] = fmaf(m.x, gc1, skipB[4*q+0]);
                skipB[4*q+1] = fmaf(m.y, gc1, skipB[4*q+1]);
                skipB[4*q+2] = fmaf(m.z, gc1, skipB[4*q+2]);
                skipB[4*q+3] = fmaf(m.w, gc1, skipB[4*q+3]);
            }
        }
        nb[p0] = a0 + dot0 + s_bo;
        nb[p1] = a1 + dot1 + s_bo;

        // ---- halo positions: stream update only (no skip) ----
        const int offn = off + 2 * d;
        for (int p = offn + tid; p < HALO; p += NTHREADS) {
            float aa = cb[p], ee = cb[p - d], ff = cb[p - 2 * d];
            float dd = 0.f;
            #pragma unroll 4
            for (int c = 0; c < 32; ++c) {
                float4 wf = *(const float4*)&s_wfg[c][0];
                float4 wg = *(const float4*)&s_wfg[c][4];
                float uf = fmaf(wf.x, ff, fmaf(wf.y, ee, fmaf(wf.z, aa, wf.w)));
                float ug = fmaf(wg.x, ff, fmaf(wg.y, ee, fmaf(wg.z, aa, wg.w)));
                dd = fmaf(s_wo[c], gatedfn(uf, ug), dd);
            }
            int g = t0 - HALO + p;
            nb[p] = (g >= 0) ? (aa + dd + s_bo) : 0.f;   // enforce causal zero-pad semantics
        }

        off = offn;
        cur ^= 1;
    }

    // ---- head: skip1 = relu(skip_pre + b1_eff); out = Wsk2 @ skip1 + b_sk2 ----
    float m0 = 0.f, v0 = 0.f, m1 = 0.f, v1 = 0.f;
    #pragma unroll
    for (int sc = 0; sc < 64; ++sc) {
        float r0 = fmaxf(skipA[sc] + s_head[sc], 0.f);
        float r1 = fmaxf(skipB[sc] + s_head[sc], 0.f);
        m0 = fmaf(s_head[64 + sc],  r0, m0);
        v0 = fmaf(s_head[128 + sc], r0, v0);
        m1 = fmaf(s_head[64 + sc],  r1, m1);
        v1 = fmaf(s_head[128 + sc], r1, v1);
    }
    const float bm = s_head[192], bs = s_head[193];
    const int t = t0 + tid;
    // output layout: means[B,T] then stds[B,T]
    out[(size_t)b * T_LEN + t]                         = m0 + bm;
    out[(size_t)(B_SZ + b) * T_LEN + t]                = expf(0.5f * (v0 + bs));
    out[(size_t)b * T_LEN + t + NTHREADS]              = m1 + bm;
    out[(size_t)(B_SZ + b) * T_LEN + t + NTHREADS]     = expf(0.5f * (v1 + bs));
}

// ---------------- launch ----------------
extern "C" void kernel_launch(void* const* d_in, const int* in_sizes, int n_in,
                              void* d_out, int out_size) {
    const float* x = (const float*)d_in[0];
    wn_precompute<<<L_LAYERS, NTHREADS>>>(
        (const float*)d_in[1],  (const float*)d_in[2],
        (const float*)d_in[3],  (const float*)d_in[4],
        (const float*)d_in[5],  (const float*)d_in[6],
        (const float*)d_in[7],  (const float*)d_in[8],
        (const float*)d_in[9],  (const float*)d_in[10],
        (const float*)d_in[11], (const float*)d_in[12],
        (const float*)d_in[13], (const float*)d_in[14]);

    dim3 grid(T_LEN / TT, B_SZ);
    wn_main<<<grid, NTHREADS>>>(x, (float*)d_out);
}

// round 5
// speedup vs baseline: 1.2037x; 1.2037x over previous
#include <cuda_runtime.h>
#include <math.h>

#define L_LAYERS 16
#define T_LEN 65536
#define B_SZ 8
#define TT 512
#define HALO 1024
#define NT (TT + HALO)
#define NTHREADS 256

typedef unsigned long long u64;

// ---------------- device scratch (precomputed folded weights) ----------------
__device__ float g_wfg[L_LAYERS][32][8];   // per channel: wf0,wf1,wf2,bf_eff, wg0,wg1,wg2,bg_eff
__device__ float g_Mt[L_LAYERS][32][64];   // M[i] = W_sk1 @ W_s[i], transposed [c][sc]
__device__ float g_wo[L_LAYERS][32];
__device__ float g_bo[L_LAYERS];
__device__ float g_head[200];              // [0:64) b1_eff, [64:128) Wsk2 row0, [128:192) row1, [192],[193] b_sk2

// ---------------- packed f32x2 helpers (sm_103a FFMA2 path) ----------------
__device__ __forceinline__ u64 pk2(float lo, float hi) {
    u64 r; asm("mov.b64 %0,{%1,%2};" : "=l"(r) : "f"(lo), "f"(hi)); return r;
}
__device__ __forceinline__ float lo2(u64 v) {
    float f; asm("{ .reg .f32 h; mov.b64 {%0,h},%1; }" : "=f"(f) : "l"(v)); return f;
}
__device__ __forceinline__ float hi2(u64 v) {
    float f; asm("{ .reg .f32 l; mov.b64 {l,%0},%1; }" : "=f"(f) : "l"(v)); return f;
}
__device__ __forceinline__ void fma2(u64& d, u64 a, u64 b) {
    asm("fma.rn.f32x2 %0,%1,%2,%0;" : "+l"(d) : "l"(a), "l"(b));
}

// ---------------- weight folding kernel ----------------
__global__ void wn_precompute(
    const float* __restrict__ W_in, const float* __restrict__ b_in,
    const float* __restrict__ W_f,  const float* __restrict__ b_f,
    const float* __restrict__ W_g,  const float* __restrict__ b_g,
    const float* __restrict__ W_s,  const float* __restrict__ b_s,
    const float* __restrict__ W_o,  const float* __restrict__ b_o,
    const float* __restrict__ W_sk1,const float* __restrict__ b_sk1,
    const float* __restrict__ W_sk2,const float* __restrict__ b_sk2)
{
    int i = blockIdx.x;
    int tid = threadIdx.x;

    for (int idx = tid; idx < 32 * 3; idx += NTHREADS) {
        int c = idx / 3, k = idx % 3;
        float sf = 0.f, sg = 0.f;
        for (int cp = 0; cp < 32; ++cp) {
            float win = W_in[i * 32 + cp];
            sf += W_f[((i * 32 + c) * 32 + cp) * 3 + k] * win;
            sg += W_g[((i * 32 + c) * 32 + cp) * 3 + k] * win;
        }
        g_wfg[i][c][k]     = sf;
        g_wfg[i][c][4 + k] = sg;
    }
    if (tid < 32) {
        int c = tid;
        float bf = b_f[i * 32 + c], bg = b_g[i * 32 + c];
        for (int k = 0; k < 3; ++k)
            for (int cp = 0; cp < 32; ++cp) {
                float bi = b_in[i * 32 + cp];
                bf += W_f[((i * 32 + c) * 32 + cp) * 3 + k] * bi;
                bg += W_g[((i * 32 + c) * 32 + cp) * 3 + k] * bi;
            }
        g_wfg[i][c][3] = bf;
        g_wfg[i][c][7] = bg;
        g_wo[i][c] = W_o[i * 32 + c];
    }
    if (tid == 0) g_bo[i] = b_o[i];

    for (int idx = tid; idx < 2048; idx += NTHREADS) {
        int c = idx >> 6, sc = idx & 63;
        float s = 0.f;
        for (int scp = 0; scp < 64; ++scp)
            s += W_sk1[sc * 64 + scp] * W_s[(i * 64 + scp) * 32 + c];
        g_Mt[i][c][sc] = s;
    }

    if (i == 0) {
        if (tid < 64) {
            int sc = tid;
            float s = b_sk1[sc];
            for (int scp = 0; scp < 64; ++scp) {
                float bsum = 0.f;
                for (int l = 0; l < L_LAYERS; ++l) bsum += b_s[l * 64 + scp];
                s += W_sk1[sc * 64 + scp] * bsum;
            }
            g_head[sc]        = s;
            g_head[64 + sc]   = W_sk2[sc];
            g_head[128 + sc]  = W_sk2[64 + sc];
        }
        if (tid == 0) { g_head[192] = b_sk2[0]; g_head[193] = b_sk2[1]; }
    }
}

// tanh(uf) * sigmoid(ug) with a single reciprocal
__device__ __forceinline__ float gatedfn(float uf, float ug) {
    float ef = __expf(2.0f * uf);
    float eg = __expf(-ug);
    float num = ef - 1.0f;
    float den = (ef + 1.0f) * (1.0f + eg);
    return __fdividef(num, den);
}

// ---------------- main kernel ----------------
__global__ __launch_bounds__(NTHREADS) void wn_main(
    const float* __restrict__ x, float* __restrict__ out)
{
    __shared__ __align__(16) float sbuf[2][NT];
    // packed weights: s_wfg2[c] = { {wf0,wg0},{wf1,wg1},{wf2,wg2},{bf,bg} } as 2x ulonglong2
    __shared__ __align__(16) u64 s_wfg2[32][4];
    __shared__ __align__(16) float s_Mt[32][64];
    __shared__ float s_wo[32];
    __shared__ float s_head[200];
    __shared__ float s_bo;

    const int b   = blockIdx.y;
    const int t0  = blockIdx.x * TT;
    const int tid = threadIdx.x;

    const float* xb = x + (size_t)b * T_LEN;
    for (int p = tid; p < NT; p += NTHREADS) {
        int g = t0 - HALO + p;
        sbuf[0][p] = (g >= 0) ? xb[g] : 0.0f;
    }
    for (int idx = tid; idx < 200; idx += NTHREADS) s_head[idx] = g_head[idx];

    // packed skip accumulators: lanes (2q, 2q+1); A = timestep tid, B = tid+256
    u64 accA[32], accB[32];
    #pragma unroll
    for (int q = 0; q < 32; ++q) { accA[q] = 0ull; accB[q] = 0ull; }

    int cur = 0;
    int off = 0;
    const int p0 = HALO + tid;
    const int p1 = HALO + tid + NTHREADS;

    for (int layer = 0; layer < L_LAYERS; ++layer) {
        const int d = 1 << (layer & 7);

        __syncthreads();
        // stage packed conv weights: s_wfg2 flat float index c*8 + j*2 + lane
        {
            float* dst = (float*)s_wfg2;       // 256 floats
            int c = tid >> 3, k = tid & 7;
            int j = k >> 1, lane = k & 1;
            dst[tid] = g_wfg[layer][c][lane ? 4 + j : j];
        }
        {   // skip matrix: 2048 floats = 512 float4
            const float4* src = (const float4*)&g_Mt[layer][0][0];
            float4* dst = (float4*)&s_Mt[0][0];
            dst[tid] = src[tid];
            dst[tid + 256] = src[tid + 256];
        }
        if (tid < 32) s_wo[tid] = g_wo[layer][tid];
        if (tid == 0) s_bo = g_bo[layer];
        __syncthreads();

        const float* cb = sbuf[cur];
        float* nb = sbuf[cur ^ 1];

        // ---- output positions: gated + skip + residual update ----
        float a0 = cb[p0], e0 = cb[p0 - d], f0 = cb[p0 - 2 * d];
        float a1 = cb[p1], e1 = cb[p1 - d], f1 = cb[p1 - 2 * d];
        u64 a0d = pk2(a0, a0), e0d = pk2(e0, e0), f0d = pk2(f0, f0);
        u64 a1d = pk2(a1, a1), e1d = pk2(e1, e1), f1d = pk2(f1, f1);
        float dot0 = 0.f, dot1 = 0.f;
        #pragma unroll 2
        for (int c = 0; c < 32; ++c) {
            ulonglong2 W01 = ((const ulonglong2*)&s_wfg2[c][0])[0]; // {wfg0, wfg1}
            ulonglong2 W23 = ((const ulonglong2*)&s_wfg2[c][0])[1]; // {wfg2, bfg}

            u64 u0 = W23.y;                    // lanes {uf, ug}
            fma2(u0, W23.x, a0d);
            fma2(u0, W01.y, e0d);
            fma2(u0, W01.x, f0d);
            u64 u1 = W23.y;
            fma2(u1, W23.x, a1d);
            fma2(u1, W01.y, e1d);
            fma2(u1, W01.x, f1d);

            float gc0 = gatedfn(lo2(u0), hi2(u0));
            float gc1 = gatedfn(lo2(u1), hi2(u1));
            float wo = s_wo[c];
            dot0 = fmaf(wo, gc0, dot0);
            dot1 = fmaf(wo, gc1, dot1);

            u64 g0d = pk2(gc0, gc0);
            u64 g1d = pk2(gc1, gc1);
            const ulonglong2* Mrow = (const ulonglong2*)&s_Mt[c][0]; // 16 x (2 packed pairs)
            #pragma unroll
            for (int q = 0; q < 16; ++q) {
                ulonglong2 m = Mrow[q];
                fma2(accA[2 * q],     m.x, g0d);
                fma2(accA[2 * q + 1], m.y, g0d);
                fma2(accB[2 * q],     m.x, g1d);
                fma2(accB[2 * q + 1], m.y, g1d);
            }
        }
        nb[p0] = a0 + dot0 + s_bo;
        nb[p1] = a1 + dot1 + s_bo;

        // ---- halo positions: stream update only (no skip) ----
        const int offn = off + 2 * d;
        for (int p = offn + tid; p < HALO; p += NTHREADS) {
            float aa = cb[p], ee = cb[p - d], ff = cb[p - 2 * d];
            u64 aad = pk2(aa, aa), eed = pk2(ee, ee), ffd = pk2(ff, ff);
            float dd = 0.f;
            #pragma unroll 4
            for (int c = 0; c < 32; ++c) {
                ulonglong2 W01 = ((const ulonglong2*)&s_wfg2[c][0])[0];
                ulonglong2 W23 = ((const ulonglong2*)&s_wfg2[c][0])[1];
                u64 u = W23.y;
                fma2(u, W23.x, aad);
                fma2(u, W01.y, eed);
                fma2(u, W01.x, ffd);
                dd = fmaf(s_wo[c], gatedfn(lo2(u), hi2(u)), dd);
            }
            int g = t0 - HALO + p;
            nb[p] = (g >= 0) ? (aa + dd + s_bo) : 0.f;
        }

        off = offn;
        cur ^= 1;
    }

    // ---- head: skip1 = relu(skip_pre + b1_eff); out = Wsk2 @ skip1 + b_sk2 ----
    float m0 = 0.f, v0 = 0.f, m1 = 0.f, v1 = 0.f;
    #pragma unroll
    for (int q = 0; q < 32; ++q) {
        int sc = 2 * q;
        float rA0 = fmaxf(lo2(accA[q]) + s_head[sc],     0.f);
        float rA1 = fmaxf(hi2(accA[q]) + s_head[sc + 1], 0.f);
        float rB0 = fmaxf(lo2(accB[q]) + s_head[sc],     0.f);
        float rB1 = fmaxf(hi2(accB[q]) + s_head[sc + 1], 0.f);
        m0 = fmaf(s_head[64 + sc],      rA0, m0);
        v0 = fmaf(s_head[128 + sc],     rA0, v0);
        m0 = fmaf(s_head[64 + sc + 1],  rA1, m0);
        v0 = fmaf(s_head[128 + sc + 1], rA1, v0);
        m1 = fmaf(s_head[64 + sc],      rB0, m1);
        v1 = fmaf(s_head[128 + sc],     rB0, v1);
        m1 = fmaf(s_head[64 + sc + 1],  rB1, m1);
        v1 = fmaf(s_head[128 + sc + 1], rB1, v1);
    }
    const float bm = s_head[192], bs = s_head[193];
    const int t = t0 + tid;
    out[(size_t)b * T_LEN + t]                     = m0 + bm;
    out[(size_t)(B_SZ + b) * T_LEN + t]            = expf(0.5f * (v0 + bs));
    out[(size_t)b * T_LEN + t + NTHREADS]          = m1 + bm;
    out[(size_t)(B_SZ + b) * T_LEN + t + NTHREADS] = expf(0.5f * (v1 + bs));
}

// ---------------- launch ----------------
extern "C" void kernel_launch(void* const* d_in, const int* in_sizes, int n_in,
                              void* d_out, int out_size) {
    const float* x = (const float*)d_in[0];
    wn_precompute<<<L_LAYERS, NTHREADS>>>(
        (const float*)d_in[1],  (const float*)d_in[2],
        (const float*)d_in[3],  (const float*)d_in[4],
        (const float*)d_in[5],  (const float*)d_in[6],
        (const float*)d_in[7],  (const float*)d_in[8],
        (const float*)d_in[9],  (const float*)d_in[10],
        (const float*)d_in[11], (const float*)d_in[12],
        (const float*)d_in[13], (const float*)d_in[14]);

    dim3 grid(T_LEN / TT, B_SZ);
    wn_main<<<grid, NTHREADS>>>(x, (float*)d_out);
}